// round 1
// baseline (speedup 1.0000x reference)
#include <cuda_runtime.h>
#include <math.h>

#define B_ 4
#define S_ 1024
#define D_ 1024
#define F_ 4096
#define E_ 8
#define K_ 2
#define T_ (B_*S_)      // 4096 tokens
#define P_ (T_*K_)      // 8192 token-expert pairs

// ---------------- device scratch (static; no allocations allowed) ----------
__device__ float g_logits[T_*E_];
__device__ int   g_topi[T_*K_];
__device__ float g_topw[T_*K_];
__device__ int   g_counts[E_];
__device__ int   g_offsets[E_];
__device__ int   g_cursor[E_];
__device__ int   g_pair_token[P_];
__device__ float g_pair_w[P_];
__device__ float g_h[(size_t)P_*F_];   // 128 MB intermediate SwiGLU activations

// ---------------- small kernels -------------------------------------------
__global__ void init_kernel() {
    int i = threadIdx.x;
    if (i < E_) { g_counts[i] = 0; g_cursor[i] = 0; }
}

// One block (128 threads) per token: logits[t][e] = x[t] . gate_w[e]
__global__ void router_kernel(const float* __restrict__ x,
                              const float* __restrict__ gw) {
    int t = blockIdx.x;
    const float* xr = x + (size_t)t * D_;
    float acc[E_];
#pragma unroll
    for (int e = 0; e < E_; e++) acc[e] = 0.f;
    for (int d = threadIdx.x; d < D_; d += blockDim.x) {
        float xv = xr[d];
#pragma unroll
        for (int e = 0; e < E_; e++) acc[e] = fmaf(xv, gw[e * D_ + d], acc[e]);
    }
#pragma unroll
    for (int e = 0; e < E_; e++)
        for (int o = 16; o > 0; o >>= 1)
            acc[e] += __shfl_down_sync(0xffffffffu, acc[e], o);
    __shared__ float s[4][E_];
    int warp = threadIdx.x >> 5, lane = threadIdx.x & 31;
    if (lane == 0) {
#pragma unroll
        for (int e = 0; e < E_; e++) s[warp][e] = acc[e];
    }
    __syncthreads();
    if (threadIdx.x < E_) {
        g_logits[t * E_ + threadIdx.x] =
            s[0][threadIdx.x] + s[1][threadIdx.x] + s[2][threadIdx.x] + s[3][threadIdx.x];
    }
}

// Per-token top-2 with renormalized softmax weights (Z cancels: w = e_i/(e0+e1)).
// Ties: strict > keeps lowest index, matching jax.lax.top_k.
__global__ void topk_kernel() {
    int t = blockIdx.x * blockDim.x + threadIdx.x;
    if (t >= T_) return;
    float l[E_];
#pragma unroll
    for (int e = 0; e < E_; e++) l[e] = g_logits[t * E_ + e];
    int i0 = 0; float m0 = l[0];
#pragma unroll
    for (int e = 1; e < E_; e++) if (l[e] > m0) { m0 = l[e]; i0 = e; }
    int i1 = -1; float m1 = -1e30f;
#pragma unroll
    for (int e = 0; e < E_; e++) if (e != i0 && l[e] > m1) { m1 = l[e]; i1 = e; }
    float e1  = expf(m1 - m0);
    float inv = 1.f / (1.f + e1);
    g_topi[t * 2 + 0] = i0; g_topw[t * 2 + 0] = inv;
    g_topi[t * 2 + 1] = i1; g_topw[t * 2 + 1] = e1 * inv;
    atomicAdd(&g_counts[i0], 1);
    atomicAdd(&g_counts[i1], 1);
}

__global__ void offsets_kernel() {
    if (threadIdx.x == 0) {
        int acc = 0;
        for (int e = 0; e < E_; e++) { g_offsets[e] = acc; acc += g_counts[e]; }
    }
}

__global__ void scatter_kernel() {
    int t = blockIdx.x * blockDim.x + threadIdx.x;
    if (t >= T_) return;
#pragma unroll
    for (int k = 0; k < K_; k++) {
        int e = g_topi[t * 2 + k];
        int p = g_offsets[e] + atomicAdd(&g_cursor[e], 1);
        g_pair_token[p] = t;
        g_pair_w[p]     = g_topw[t * 2 + k];
    }
}

// rl[b][e] = mean over S of logits. One block (256 thr) per (b,e).
__global__ void rl_kernel(float* __restrict__ out_rl) {
    int b = blockIdx.x >> 3, e = blockIdx.x & 7;
    float acc = 0.f;
    for (int s = threadIdx.x; s < S_; s += blockDim.x)
        acc += g_logits[(b * S_ + s) * E_ + e];
    for (int o = 16; o > 0; o >>= 1)
        acc += __shfl_down_sync(0xffffffffu, acc, o);
    __shared__ float sm[8];
    int warp = threadIdx.x >> 5, lane = threadIdx.x & 31;
    if (lane == 0) sm[warp] = acc;
    __syncthreads();
    if (threadIdx.x == 0) {
        float v = 0.f;
        for (int w = 0; w < 8; w++) v += sm[w];
        out_rl[b * E_ + e] = v * (1.f / S_);
    }
}

// ---------------- tiled fp32 GEMMs ----------------------------------------
#define TM 64
#define TN 64
#define TKD 16

// h[pair, F] = silu(x_g @ w1[e]) * (x_g @ w3[e]) over this expert's token list
__global__ __launch_bounds__(256)
void gemm1_kernel(const float* __restrict__ x,
                  const float* __restrict__ w1,
                  const float* __restrict__ w3) {
    int e = blockIdx.z;
    int cnt = g_counts[e];
    int m0 = blockIdx.y * TM;
    if (m0 >= cnt) return;
    int base = g_offsets[e];
    int n0 = blockIdx.x * TN;

    __shared__ float xs[TKD][TM];
    __shared__ float w1s[TKD][TN];
    __shared__ float w3s[TKD][TN];

    int tid = threadIdx.x;
    int tx = tid & 15, ty = tid >> 4;

    int lm = tid >> 2;          // 0..63 : row within tile this thread loads
    int lk = (tid & 3) * 4;     // 0,4,8,12
    int row = m0 + lm;
    int rclamp = min(row, cnt - 1);
    int tok = g_pair_token[base + rclamp];
    const float* xrow = x + (size_t)tok * D_;

    int wk = tid >> 4;          // 0..15
    int wn = (tid & 15) * 4;
    const float* w1b = w1 + (size_t)e * D_ * F_;
    const float* w3b = w3 + (size_t)e * D_ * F_;

    float acc1[4][4], acc3[4][4];
#pragma unroll
    for (int i = 0; i < 4; i++)
#pragma unroll
        for (int j = 0; j < 4; j++) { acc1[i][j] = 0.f; acc3[i][j] = 0.f; }

    for (int d0 = 0; d0 < D_; d0 += TKD) {
        float4 xv = *(const float4*)(xrow + d0 + lk);
        xs[lk + 0][lm] = xv.x; xs[lk + 1][lm] = xv.y;
        xs[lk + 2][lm] = xv.z; xs[lk + 3][lm] = xv.w;
        *(float4*)&w1s[wk][wn] = *(const float4*)(w1b + (size_t)(d0 + wk) * F_ + n0 + wn);
        *(float4*)&w3s[wk][wn] = *(const float4*)(w3b + (size_t)(d0 + wk) * F_ + n0 + wn);
        __syncthreads();
#pragma unroll
        for (int kk = 0; kk < TKD; kk++) {
            float4 av = *(const float4*)&xs[kk][ty * 4];
            float4 b1 = *(const float4*)&w1s[kk][tx * 4];
            float4 b3 = *(const float4*)&w3s[kk][tx * 4];
            float a[4]  = {av.x, av.y, av.z, av.w};
            float v1[4] = {b1.x, b1.y, b1.z, b1.w};
            float v3[4] = {b3.x, b3.y, b3.z, b3.w};
#pragma unroll
            for (int i = 0; i < 4; i++)
#pragma unroll
                for (int j = 0; j < 4; j++) {
                    acc1[i][j] = fmaf(a[i], v1[j], acc1[i][j]);
                    acc3[i][j] = fmaf(a[i], v3[j], acc3[i][j]);
                }
        }
        __syncthreads();
    }
#pragma unroll
    for (int i = 0; i < 4; i++) {
        int r = m0 + ty * 4 + i;
        if (r < cnt) {
            float* hp = &g_h[(size_t)(base + r) * F_ + n0 + tx * 4];
#pragma unroll
            for (int j = 0; j < 4; j++) {
                float g = acc1[i][j];
                float s = g / (1.f + expf(-g));   // silu
                hp[j] = s * acc3[i][j];
            }
        }
    }
}

// out[token] += combine_w * (h[pair] @ w2[e]); exactly 2 atomic adds per elem
__global__ __launch_bounds__(256)
void gemm2_kernel(const float* __restrict__ w2, float* __restrict__ out) {
    int e = blockIdx.z;
    int cnt = g_counts[e];
    int m0 = blockIdx.y * TM;
    if (m0 >= cnt) return;
    int base = g_offsets[e];
    int n0 = blockIdx.x * TN;

    __shared__ float hs[TKD][TM];
    __shared__ float ws[TKD][TN];

    int tid = threadIdx.x;
    int tx = tid & 15, ty = tid >> 4;

    int lm = tid >> 2;
    int lk = (tid & 3) * 4;
    int row = m0 + lm;
    int rclamp = min(row, cnt - 1);
    const float* hrow = &g_h[(size_t)(base + rclamp) * F_];

    int wk = tid >> 4;
    int wn = (tid & 15) * 4;
    const float* w2b = w2 + (size_t)e * F_ * D_;

    float acc[4][4];
#pragma unroll
    for (int i = 0; i < 4; i++)
#pragma unroll
        for (int j = 0; j < 4; j++) acc[i][j] = 0.f;

    for (int f0 = 0; f0 < F_; f0 += TKD) {
        float4 hv = *(const float4*)(hrow + f0 + lk);
        hs[lk + 0][lm] = hv.x; hs[lk + 1][lm] = hv.y;
        hs[lk + 2][lm] = hv.z; hs[lk + 3][lm] = hv.w;
        *(float4*)&ws[wk][wn] = *(const float4*)(w2b + (size_t)(f0 + wk) * D_ + n0 + wn);
        __syncthreads();
#pragma unroll
        for (int kk = 0; kk < TKD; kk++) {
            float4 av = *(const float4*)&hs[kk][ty * 4];
            float4 bv = *(const float4*)&ws[kk][tx * 4];
            float a[4] = {av.x, av.y, av.z, av.w};
            float b[4] = {bv.x, bv.y, bv.z, bv.w};
#pragma unroll
            for (int i = 0; i < 4; i++)
#pragma unroll
                for (int j = 0; j < 4; j++)
                    acc[i][j] = fmaf(a[i], b[j], acc[i][j]);
        }
        __syncthreads();
    }
#pragma unroll
    for (int i = 0; i < 4; i++) {
        int r = m0 + ty * 4 + i;
        if (r < cnt) {
            int p = base + r;
            int tok = g_pair_token[p];
            float wgt = g_pair_w[p];
            float* op = &out[(size_t)tok * D_ + n0 + tx * 4];
#pragma unroll
            for (int j = 0; j < 4; j++)
                atomicAdd(op + j, acc[i][j] * wgt);
        }
    }
}

// ---------------- launch ---------------------------------------------------
extern "C" void kernel_launch(void* const* d_in, const int* in_sizes, int n_in,
                              void* d_out, int out_size) {
    const float* x  = (const float*)d_in[0];   // hidden_states [B,S,D]
    const float* gw = (const float*)d_in[1];   // gate_w [E,D]
    const float* w1 = (const float*)d_in[2];   // [E,D,F]
    const float* w3 = (const float*)d_in[3];   // [E,D,F]
    const float* w2 = (const float*)d_in[4];   // [E,F,D]
    float* out    = (float*)d_out;             // [B,S,D] then [B,E]
    float* out_rl = out + (size_t)T_ * D_;

    cudaMemsetAsync(out, 0, (size_t)T_ * D_ * sizeof(float));
    init_kernel<<<1, 32>>>();
    router_kernel<<<T_, 128>>>(x, gw);
    topk_kernel<<<T_ / 256, 256>>>();
    offsets_kernel<<<1, 32>>>();
    scatter_kernel<<<T_ / 256, 256>>>();
    rl_kernel<<<B_ * E_, 256>>>(out_rl);
    gemm1_kernel<<<dim3(F_ / TN, T_ / TM, E_), 256>>>(x, w1, w3);
    gemm2_kernel<<<dim3(D_ / TN, T_ / TM, E_), 256>>>(w2, out);
}

// round 4
// speedup vs baseline: 2.4177x; 2.4177x over previous
#include <cuda_runtime.h>
#include <cuda_bf16.h>
#include <cstdint>
#include <math.h>

#define B_ 4
#define S_ 1024
#define D_ 1024
#define F_ 4096
#define E_ 8
#define K_ 2
#define T_ (B_*S_)      // 4096 tokens
#define P_ (T_*K_)      // 8192 token-expert pairs

// ---------------- device scratch ------------------------------------------
__device__ float g_logits[T_*E_];
__device__ int   g_topi[T_*K_];
__device__ float g_topw[T_*K_];
__device__ int   g_counts[E_];
__device__ int   g_offsets[E_];
__device__ int   g_cursor[E_];
__device__ int   g_pair_token[P_];
__device__ float g_pair_w[P_];
__device__ float g_h[(size_t)P_*F_];   // 128 MB SwiGLU activations

// ---------------- helpers --------------------------------------------------
__device__ __forceinline__ uint32_t smem_u32(const void* p) {
    uint32_t a;
    asm("{ .reg .u64 t; cvta.to.shared.u64 t, %1; cvt.u32.u64 %0, t; }"
        : "=r"(a) : "l"(p));
    return a;
}

#define LDSM4(R, addr) \
    asm volatile("ldmatrix.sync.aligned.m8n8.x4.shared.b16 {%0,%1,%2,%3}, [%4];" \
        : "=r"((R)[0]), "=r"((R)[1]), "=r"((R)[2]), "=r"((R)[3]) : "r"(addr))

#define LDSM4T(R, addr) \
    asm volatile("ldmatrix.sync.aligned.m8n8.x4.trans.shared.b16 {%0,%1,%2,%3}, [%4];" \
        : "=r"((R)[0]), "=r"((R)[1]), "=r"((R)[2]), "=r"((R)[3]) : "r"(addr))

#define MMA(D, A, B0, B1) \
    asm volatile("mma.sync.aligned.m16n8k16.row.col.f32.bf16.bf16.f32 " \
        "{%0,%1,%2,%3},{%4,%5,%6,%7},{%8,%9},{%0,%1,%2,%3};" \
        : "+f"((D)[0]), "+f"((D)[1]), "+f"((D)[2]), "+f"((D)[3]) \
        : "r"((A)[0]), "r"((A)[1]), "r"((A)[2]), "r"((A)[3]), "r"(B0), "r"(B1))

__device__ __forceinline__ uint32_t bfpack(__nv_bfloat162 h) {
    return *reinterpret_cast<uint32_t*>(&h);
}

// split float4 into bf16 hi (rounded) and bf16 lo (residual)
__device__ __forceinline__ void split4(float4 v, uint2& hi, uint2& lo) {
    __nv_bfloat162 hxy = __floats2bfloat162_rn(v.x, v.y);
    __nv_bfloat162 hzw = __floats2bfloat162_rn(v.z, v.w);
    float2 fxy = __bfloat1622float2(hxy);
    float2 fzw = __bfloat1622float2(hzw);
    __nv_bfloat162 lxy = __floats2bfloat162_rn(v.x - fxy.x, v.y - fxy.y);
    __nv_bfloat162 lzw = __floats2bfloat162_rn(v.z - fzw.x, v.w - fzw.y);
    hi.x = bfpack(hxy); hi.y = bfpack(hzw);
    lo.x = bfpack(lxy); lo.y = bfpack(lzw);
}

// ---------------- small kernels --------------------------------------------
__global__ void init_kernel() {
    int i = threadIdx.x;
    if (i < E_) { g_counts[i] = 0; g_cursor[i] = 0; }
}

__global__ void router_kernel(const float* __restrict__ x,
                              const float* __restrict__ gw) {
    int t = blockIdx.x;
    const float* xr = x + (size_t)t * D_;
    float acc[E_];
#pragma unroll
    for (int e = 0; e < E_; e++) acc[e] = 0.f;
    for (int d = threadIdx.x; d < D_; d += blockDim.x) {
        float xv = xr[d];
#pragma unroll
        for (int e = 0; e < E_; e++) acc[e] = fmaf(xv, gw[e * D_ + d], acc[e]);
    }
#pragma unroll
    for (int e = 0; e < E_; e++)
        for (int o = 16; o > 0; o >>= 1)
            acc[e] += __shfl_down_sync(0xffffffffu, acc[e], o);
    __shared__ float s[4][E_];
    int warp = threadIdx.x >> 5, lane = threadIdx.x & 31;
    if (lane == 0) {
#pragma unroll
        for (int e = 0; e < E_; e++) s[warp][e] = acc[e];
    }
    __syncthreads();
    if (threadIdx.x < E_) {
        g_logits[t * E_ + threadIdx.x] =
            s[0][threadIdx.x] + s[1][threadIdx.x] + s[2][threadIdx.x] + s[3][threadIdx.x];
    }
}

__global__ void topk_kernel() {
    int t = blockIdx.x * blockDim.x + threadIdx.x;
    if (t >= T_) return;
    float l[E_];
#pragma unroll
    for (int e = 0; e < E_; e++) l[e] = g_logits[t * E_ + e];
    int i0 = 0; float m0 = l[0];
#pragma unroll
    for (int e = 1; e < E_; e++) if (l[e] > m0) { m0 = l[e]; i0 = e; }
    int i1 = -1; float m1 = -1e30f;
#pragma unroll
    for (int e = 0; e < E_; e++) if (e != i0 && l[e] > m1) { m1 = l[e]; i1 = e; }
    float e1  = expf(m1 - m0);
    float inv = 1.f / (1.f + e1);
    g_topi[t * 2 + 0] = i0; g_topw[t * 2 + 0] = inv;
    g_topi[t * 2 + 1] = i1; g_topw[t * 2 + 1] = e1 * inv;
    atomicAdd(&g_counts[i0], 1);
    atomicAdd(&g_counts[i1], 1);
}

__global__ void offsets_kernel() {
    if (threadIdx.x == 0) {
        int acc = 0;
        for (int e = 0; e < E_; e++) { g_offsets[e] = acc; acc += g_counts[e]; }
    }
}

__global__ void scatter_kernel() {
    int t = blockIdx.x * blockDim.x + threadIdx.x;
    if (t >= T_) return;
#pragma unroll
    for (int k = 0; k < K_; k++) {
        int e = g_topi[t * 2 + k];
        int p = g_offsets[e] + atomicAdd(&g_cursor[e], 1);
        g_pair_token[p] = t;
        g_pair_w[p]     = g_topw[t * 2 + k];
    }
}

__global__ void rl_kernel(float* __restrict__ out_rl) {
    int b = blockIdx.x >> 3, e = blockIdx.x & 7;
    float acc = 0.f;
    for (int s = threadIdx.x; s < S_; s += blockDim.x)
        acc += g_logits[(b * S_ + s) * E_ + e];
    for (int o = 16; o > 0; o >>= 1)
        acc += __shfl_down_sync(0xffffffffu, acc, o);
    __shared__ float sm[8];
    int warp = threadIdx.x >> 5, lane = threadIdx.x & 31;
    if (lane == 0) sm[warp] = acc;
    __syncthreads();
    if (threadIdx.x == 0) {
        float v = 0.f;
        for (int w = 0; w < 8; w++) v += sm[w];
        out_rl[b * E_ + e] = v * (1.f / S_);
    }
}

// ---------------- mma.sync GEMMs -------------------------------------------
// CTA tile 128x128, 512 threads, 4x4 warps of 32x32 warp tiles.
// K chunk = 16. A smem: [128 rows][24 bf16] (48B rows), B smem: [16 k][136 bf16].
#define A_STRIDE 48          // bytes per A smem row (16 bf16 + 8 pad)
#define B_STRIDE 272         // bytes per B smem row (128 bf16 + 8 pad)
#define A_T 6144             // 128*48
#define B_T 4352             // 16*272
#define G1_ST (2*A_T + 4*B_T)   // 29696 per stage
#define G2_ST (2*A_T + 2*B_T)   // 20992 per stage
#define G1_SMEM (2*G1_ST)       // 59392
#define G2_SMEM (2*G2_ST)       // 41984
#define NCH1 (D_/16)            // 64
#define NCH2 (F_/16)            // 256

__device__ __forceinline__ float silu(float g) {
    return g / (1.f + expf(-g));
}

// GEMM1: h = silu(xg @ w1) * (xg @ w3)
__global__ __launch_bounds__(512)
void gemm1_mma(const float* __restrict__ x,
               const float* __restrict__ w1, const float* __restrict__ w3) {
    extern __shared__ char smem[];
    int e = blockIdx.z;
    int cnt = g_counts[e];
    int m0 = blockIdx.x * 128;
    if (m0 >= cnt) return;
    int base = g_offsets[e];
    int n0 = blockIdx.y * 128;
    const float* w1b = w1 + (size_t)e * D_ * F_;
    const float* w3b = w3 + (size_t)e * D_ * F_;

    int tid = threadIdx.x;
    // loader coords
    int arow = tid >> 2, ac4 = tid & 3;
    int rcl = min(m0 + arow, cnt - 1);
    const float* aptr = x + (size_t)g_pair_token[base + rcl] * D_ + ac4 * 4;
    int bk = tid >> 5, bn4 = tid & 31;
    const float* b1ptr = w1b + (size_t)bk * F_ + n0 + bn4 * 4;
    const float* b3ptr = w3b + (size_t)bk * F_ + n0 + bn4 * 4;

    uint32_t sb = smem_u32(smem);
    int wid = tid >> 5, lane = tid & 31;
    int wm = wid & 3, wn = wid >> 2;
    // ldmatrix lane addressing
    int la_row = (lane & 7) + ((lane >> 3) & 1) * 8;
    int la_k   = (lane >> 4) * 8;
    uint32_t aoff = (uint32_t)((wm * 32 + la_row) * A_STRIDE + la_k * 2);
    int lb_k = (lane & 7) + ((lane >> 3) & 1) * 8;
    int lb_n = (lane >> 4) * 8;
    uint32_t boff = (uint32_t)(lb_k * B_STRIDE + (wn * 32 + lb_n) * 2);

    float acc1[2][4][4], acc3[2][4][4];
#pragma unroll
    for (int mt = 0; mt < 2; mt++)
#pragma unroll
        for (int nt = 0; nt < 4; nt++)
#pragma unroll
            for (int c = 0; c < 4; c++) { acc1[mt][nt][c] = 0.f; acc3[mt][nt][c] = 0.f; }

    float4 pa, pb1, pb3;
    auto ldg = [&](int c) {
        int kg = c * 16;
        pa  = *(const float4*)(aptr + kg);
        pb1 = *(const float4*)(b1ptr + (size_t)kg * F_);
        pb3 = *(const float4*)(b3ptr + (size_t)kg * F_);
    };
    auto sts = [&](int s) {
        char* st = smem + s * G1_ST;
        uint2 hi, lo;
        split4(pa, hi, lo);
        *(uint2*)(st + arow * A_STRIDE + ac4 * 8) = hi;
        *(uint2*)(st + A_T + arow * A_STRIDE + ac4 * 8) = lo;
        split4(pb1, hi, lo);
        char* b1s = st + 2 * A_T;
        *(uint2*)(b1s + bk * B_STRIDE + bn4 * 8) = hi;
        *(uint2*)(b1s + B_T + bk * B_STRIDE + bn4 * 8) = lo;
        split4(pb3, hi, lo);
        char* b3s = st + 2 * A_T + 2 * B_T;
        *(uint2*)(b3s + bk * B_STRIDE + bn4 * 8) = hi;
        *(uint2*)(b3s + B_T + bk * B_STRIDE + bn4 * 8) = lo;
    };
    auto compute = [&](int s) {
        uint32_t stb = sb + s * G1_ST;
        uint32_t Ah = stb + aoff;
        uint32_t Bb = stb + 2 * A_T + boff;
        uint32_t ah[2][4], al[2][4];
        LDSM4(ah[0], Ah);
        LDSM4(ah[1], Ah + 16 * A_STRIDE);
        LDSM4(al[0], Ah + A_T);
        LDSM4(al[1], Ah + A_T + 16 * A_STRIDE);
#pragma unroll
        for (int ng = 0; ng < 2; ng++) {
            uint32_t bh[4], bl[4];
            LDSM4T(bh, Bb + ng * 32);
            LDSM4T(bl, Bb + B_T + ng * 32);
#pragma unroll
            for (int mt = 0; mt < 2; mt++)
#pragma unroll
                for (int j = 0; j < 2; j++) {
                    int nt = ng * 2 + j;
                    MMA(acc1[mt][nt], ah[mt], bh[2 * j], bh[2 * j + 1]);
                    MMA(acc1[mt][nt], al[mt], bh[2 * j], bh[2 * j + 1]);
                    MMA(acc1[mt][nt], ah[mt], bl[2 * j], bl[2 * j + 1]);
                }
            LDSM4T(bh, Bb + 2 * B_T + ng * 32);
            LDSM4T(bl, Bb + 3 * B_T + ng * 32);
#pragma unroll
            for (int mt = 0; mt < 2; mt++)
#pragma unroll
                for (int j = 0; j < 2; j++) {
                    int nt = ng * 2 + j;
                    MMA(acc3[mt][nt], ah[mt], bh[2 * j], bh[2 * j + 1]);
                    MMA(acc3[mt][nt], al[mt], bh[2 * j], bh[2 * j + 1]);
                    MMA(acc3[mt][nt], ah[mt], bl[2 * j], bl[2 * j + 1]);
                }
        }
    };

    ldg(0); sts(0); __syncthreads();
#pragma unroll 1
    for (int c = 0; c < NCH1; c++) {
        if (c + 1 < NCH1) ldg(c + 1);
        compute(c & 1);
        if (c + 1 < NCH1) sts((c + 1) & 1);
        __syncthreads();
    }

    // epilogue: silu(acc1)*acc3 -> g_h
    int r0  = m0 + wm * 32 + (lane >> 2);
    int col = n0 + wn * 32 + (lane & 3) * 2;
#pragma unroll
    for (int mt = 0; mt < 2; mt++) {
        int ra = r0 + mt * 16;
#pragma unroll
        for (int nt = 0; nt < 4; nt++) {
            int cc = col + nt * 8;
            if (ra < cnt) {
                float2 v;
                v.x = silu(acc1[mt][nt][0]) * acc3[mt][nt][0];
                v.y = silu(acc1[mt][nt][1]) * acc3[mt][nt][1];
                *(float2*)(g_h + (size_t)(base + ra) * F_ + cc) = v;
            }
            if (ra + 8 < cnt) {
                float2 v;
                v.x = silu(acc1[mt][nt][2]) * acc3[mt][nt][2];
                v.y = silu(acc1[mt][nt][3]) * acc3[mt][nt][3];
                *(float2*)(g_h + (size_t)(base + ra + 8) * F_ + cc) = v;
            }
        }
    }
}

// GEMM2: out[token] += w * (h @ w2)
__global__ __launch_bounds__(512)
void gemm2_mma(const float* __restrict__ w2, float* __restrict__ out) {
    extern __shared__ char smem[];
    int e = blockIdx.z;
    int cnt = g_counts[e];
    int m0 = blockIdx.x * 128;
    if (m0 >= cnt) return;
    int base = g_offsets[e];
    int n0 = blockIdx.y * 128;
    const float* w2b = w2 + (size_t)e * F_ * D_;

    int tid = threadIdx.x;
    int arow = tid >> 2, ac4 = tid & 3;
    int rcl = min(m0 + arow, cnt - 1);
    const float* aptr = g_h + (size_t)(base + rcl) * F_ + ac4 * 4;
    int bk = tid >> 5, bn4 = tid & 31;
    const float* bptr = w2b + (size_t)bk * D_ + n0 + bn4 * 4;

    uint32_t sb = smem_u32(smem);
    int wid = tid >> 5, lane = tid & 31;
    int wm = wid & 3, wn = wid >> 2;
    int la_row = (lane & 7) + ((lane >> 3) & 1) * 8;
    int la_k   = (lane >> 4) * 8;
    uint32_t aoff = (uint32_t)((wm * 32 + la_row) * A_STRIDE + la_k * 2);
    int lb_k = (lane & 7) + ((lane >> 3) & 1) * 8;
    int lb_n = (lane >> 4) * 8;
    uint32_t boff = (uint32_t)(lb_k * B_STRIDE + (wn * 32 + lb_n) * 2);

    float acc[2][4][4];
#pragma unroll
    for (int mt = 0; mt < 2; mt++)
#pragma unroll
        for (int nt = 0; nt < 4; nt++)
#pragma unroll
            for (int c = 0; c < 4; c++) acc[mt][nt][c] = 0.f;

    float4 pa, pb;
    auto ldg = [&](int c) {
        int kg = c * 16;
        pa = *(const float4*)(aptr + kg);
        pb = *(const float4*)(bptr + (size_t)kg * D_);
    };
    auto sts = [&](int s) {
        char* st = smem + s * G2_ST;
        uint2 hi, lo;
        split4(pa, hi, lo);
        *(uint2*)(st + arow * A_STRIDE + ac4 * 8) = hi;
        *(uint2*)(st + A_T + arow * A_STRIDE + ac4 * 8) = lo;
        split4(pb, hi, lo);
        char* bs = st + 2 * A_T;
        *(uint2*)(bs + bk * B_STRIDE + bn4 * 8) = hi;
        *(uint2*)(bs + B_T + bk * B_STRIDE + bn4 * 8) = lo;
    };
    auto compute = [&](int s) {
        uint32_t stb = sb + s * G2_ST;
        uint32_t Ah = stb + aoff;
        uint32_t Bb = stb + 2 * A_T + boff;
        uint32_t ah[2][4], al[2][4];
        LDSM4(ah[0], Ah);
        LDSM4(ah[1], Ah + 16 * A_STRIDE);
        LDSM4(al[0], Ah + A_T);
        LDSM4(al[1], Ah + A_T + 16 * A_STRIDE);
#pragma unroll
        for (int ng = 0; ng < 2; ng++) {
            uint32_t bh[4], bl[4];
            LDSM4T(bh, Bb + ng * 32);
            LDSM4T(bl, Bb + B_T + ng * 32);
#pragma unroll
            for (int mt = 0; mt < 2; mt++)
#pragma unroll
                for (int j = 0; j < 2; j++) {
                    int nt = ng * 2 + j;
                    MMA(acc[mt][nt], ah[mt], bh[2 * j], bh[2 * j + 1]);
                    MMA(acc[mt][nt], al[mt], bh[2 * j], bh[2 * j + 1]);
                    MMA(acc[mt][nt], ah[mt], bl[2 * j], bl[2 * j + 1]);
                }
        }
    };

    ldg(0); sts(0); __syncthreads();
#pragma unroll 1
    for (int c = 0; c < NCH2; c++) {
        if (c + 1 < NCH2) ldg(c + 1);
        compute(c & 1);
        if (c + 1 < NCH2) sts((c + 1) & 1);
        __syncthreads();
    }

    int r0  = m0 + wm * 32 + (lane >> 2);
    int col = n0 + wn * 32 + (lane & 3) * 2;
#pragma unroll
    for (int mt = 0; mt < 2; mt++) {
#pragma unroll
        for (int half = 0; half < 2; half++) {
            int ra = r0 + mt * 16 + half * 8;
            if (ra < cnt) {
                int p = base + ra;
                int tok = g_pair_token[p];
                float wgt = g_pair_w[p];
                float* op = out + (size_t)tok * D_;
#pragma unroll
                for (int nt = 0; nt < 4; nt++) {
                    int cc = col + nt * 8;
                    atomicAdd(op + cc,     acc[mt][nt][2 * half]     * wgt);
                    atomicAdd(op + cc + 1, acc[mt][nt][2 * half + 1] * wgt);
                }
            }
        }
    }
}

// ---------------- launch ---------------------------------------------------
extern "C" void kernel_launch(void* const* d_in, const int* in_sizes, int n_in,
                              void* d_out, int out_size) {
    const float* x  = (const float*)d_in[0];
    const float* gw = (const float*)d_in[1];
    const float* w1 = (const float*)d_in[2];
    const float* w3 = (const float*)d_in[3];
    const float* w2 = (const float*)d_in[4];
    float* out    = (float*)d_out;
    float* out_rl = out + (size_t)T_ * D_;

    static int configured = 0;
    cudaFuncSetAttribute(gemm1_mma, cudaFuncAttributeMaxDynamicSharedMemorySize, G1_SMEM);
    cudaFuncSetAttribute(gemm2_mma, cudaFuncAttributeMaxDynamicSharedMemorySize, G2_SMEM);
    (void)configured;

    cudaMemsetAsync(out, 0, (size_t)T_ * D_ * sizeof(float));
    init_kernel<<<1, 32>>>();
    router_kernel<<<T_, 128>>>(x, gw);
    topk_kernel<<<T_ / 256, 256>>>();
    offsets_kernel<<<1, 32>>>();
    scatter_kernel<<<T_ / 256, 256>>>();
    rl_kernel<<<B_ * E_, 256>>>(out_rl);

    gemm1_mma<<<dim3(32, F_ / 128, E_), 512, G1_SMEM>>>(x, w1, w3);
    gemm2_mma<<<dim3(32, D_ / 128, E_), 512, G2_SMEM>>>(w2, out);
}